// round 1
// baseline (speedup 1.0000x reference)
#include <cuda_runtime.h>
#include <cub/cub.cuh>
#include <cstdint>

// Problem constants (fixed shapes from reference)
#define NB   5
#define HWPX 65536          // 256*256
#define NP   (NB*HWPX)      // 327680 pixels total
#define NCH  256
#define NBLK (NP/1024)      // 320 scan blocks, 64 per batch

// ---- static device scratch (allocation-free) ----
__device__ unsigned long long g_keys_in[NP];
__device__ unsigned long long g_keys_out[NP];
__device__ float          g_bestu[NP];
__device__ unsigned char  g_g8[NP];
__device__ signed char    g_selmap[NP];   // 0,1,2 accepted group; -1 rejected
__device__ int            g_S[NP];        // inclusive cost prefix (sorted order)
__device__ int            g_blockSums[NBLK];
__device__ int            g_blockOff[NBLK];
__device__ int            g_i1[NB];       // first-rejection sorted index per batch
__device__ unsigned char  g_temp[64u*1024u*1024u]; // cub temp storage

__device__ __forceinline__ float load_budget(const void* ptr) {
    // Input scalar may be int32 or float32; disambiguate by plausibility.
    int iv = *(const int*)ptr;
    if (iv > 0 && iv < 100000000) return (float)iv;
    return __int_as_float(iv);
}

__device__ __forceinline__ int cost_of(int g) { return (g == 0) ? 4 : (g == 1) ? 2 : 1; }

// ---- Kernel A: per-pixel argmax + sort key ----
__global__ void kArgmax(const float* __restrict__ util) {
    int p = blockIdx.x * blockDim.x + threadIdx.x;
    if (p >= NP) return;
    float u0 = util[3*p], u1 = util[3*p+1], u2 = util[3*p+2];
    int g = 0; float bu = u0;
    if (u1 > bu) { bu = u1; g = 1; }   // strict > : first max wins (matches jnp.argmax)
    if (u2 > bu) { bu = u2; g = 2; }
    g_bestu[p] = bu;
    g_g8[p]    = (unsigned char)g;
    unsigned int x   = __float_as_uint(bu);
    unsigned int ord = (x & 0x80000000u) ? ~x : (x | 0x80000000u); // ascending-order map
    unsigned int dsc = ~ord;                                       // descending u
    unsigned long long b   = (unsigned long long)(p >> 16);
    unsigned long long pix = (unsigned long long)(p & 0xFFFF);
    g_keys_in[p] = (b << 48) | ((unsigned long long)dsc << 16) | pix;
}

// ---- Scan pass 1: per-1024-item block cost sums over sorted order ----
__global__ void kScan1() {
    __shared__ int sh[256];
    int bi = blockIdx.x, t = threadIdx.x;
    int base = bi * 1024 + t * 4;
    int s = 0;
    #pragma unroll
    for (int k = 0; k < 4; k++) {
        unsigned long long key = g_keys_out[base + k];
        int p = (int)(key >> 48) * HWPX + (int)(key & 0xFFFFu);
        if (g_bestu[p] > 0.0f) s += cost_of((int)g_g8[p]);
    }
    sh[t] = s; __syncthreads();
    for (int off = 128; off > 0; off >>= 1) {
        if (t < off) sh[t] += sh[t + off];
        __syncthreads();
    }
    if (t == 0) g_blockSums[bi] = sh[0];
}

// ---- Scan pass 2: exclusive offsets across blocks (per batch), init g_i1 ----
__global__ void kScan2() {
    int t = threadIdx.x;
    if (t < NB) g_i1[t] = 0x7FFFFFFF;
    if (t < NBLK) {
        int start = (t >> 6) << 6;   // 64 blocks per batch
        int s = 0;
        for (int j = start; j < t; j++) s += g_blockSums[j];
        g_blockOff[t] = s;
    }
}

// ---- Scan pass 3: per-item prefix, phase-1 accept, find first rejection ----
__global__ void kScan3(const void* __restrict__ budget_p, float* __restrict__ out_sel) {
    __shared__ int sh[256];
    float budget = load_budget(budget_p) / (float)NB;
    int bi = blockIdx.x, t = threadIdx.x;
    int batch = bi >> 6;
    int base = bi * 1024 + t * 4;
    int c[4], p4[4], g4[4]; bool v[4];
    int s = 0;
    #pragma unroll
    for (int k = 0; k < 4; k++) {
        unsigned long long key = g_keys_out[base + k];
        int p = (int)(key >> 48) * HWPX + (int)(key & 0xFFFFu);
        bool valid = g_bestu[p] > 0.0f;
        int g = (int)g_g8[p];
        int cc = valid ? cost_of(g) : 0;
        p4[k] = p; g4[k] = g; v[k] = valid; c[k] = cc; s += cc;
    }
    sh[t] = s; __syncthreads();
    for (int off = 1; off < 256; off <<= 1) {
        int a = (t >= off) ? sh[t - off] : 0;
        __syncthreads();
        sh[t] += a;
        __syncthreads();
    }
    int run = g_blockOff[bi] + sh[t] - s;   // exclusive prefix for this thread
    #pragma unroll
    for (int k = 0; k < 4; k++) {
        run += c[k];
        g_S[base + k] = run;
        bool acc = v[k] && ((float)run <= budget);
        g_selmap[p4[k]] = acc ? (signed char)g4[k] : (signed char)-1;
        out_sel[p4[k]]  = acc ? (float)g4[k] : -1.0f;
        if (v[k] && !acc) atomicMin(&g_i1[batch], base + k);
    }
}

// ---- Fixup: exact greedy replay from first rejection (<=3 more accepts possible) ----
__global__ void kFixup(const void* __restrict__ budget_p, float* __restrict__ out_sel) {
    if (threadIdx.x != 0) return;
    int b = blockIdx.x;
    float budget = load_budget(budget_p) / (float)NB;
    int i1 = g_i1[b];
    if (i1 == 0x7FFFFFFF) return;
    {   // usage just before the first rejected (valid) item
        unsigned long long key = g_keys_out[i1];
        int p = (int)(key >> 48) * HWPX + (int)(key & 0xFFFFu);
        int cr = cost_of((int)g_g8[p]);
        float usage = (float)(g_S[i1] - cr);
        int end = (b + 1) * HWPX;
        for (int i = i1; i < end; i++) {
            if (usage + 1.0f > budget) break;   // no cost fits anymore
            key = g_keys_out[i];
            p = (int)(key >> 48) * HWPX + (int)(key & 0xFFFFu);
            if (g_bestu[p] > 0.0f) {
                int g = (int)g_g8[p];
                float cf = (float)cost_of(g);
                if (usage + cf <= budget) {
                    usage += cf;
                    g_selmap[p] = (signed char)g;
                    out_sel[p]  = (float)g;
                }
            }
        }
    }
}

// ---- Big kernel: masked channel copy, float4, predicated reads ----
__global__ void kMaskedCopy(const float* __restrict__ collab, float* __restrict__ out) {
    int tid = blockIdx.x * blockDim.x + threadIdx.x;  // 20,971,520 threads
    int row = tid >> 14;               // (b*256 + c), 16384 float4 per row
    int o   = (tid & 16383) << 2;      // hw offset (multiple of 4)
    int c   = row & 255;
    int b   = row >> 8;
    int grp = (c < 64) ? 0 : (c < 192) ? 1 : 2;
    char4 s4 = *(const char4*)(g_selmap + b * HWPX + o);
    bool m0 = (s4.x == grp), m1 = (s4.y == grp), m2 = (s4.z == grp), m3 = (s4.w == grp);
    float4 v = make_float4(0.f, 0.f, 0.f, 0.f);
    size_t idx = ((size_t)row << 16) + (size_t)o;
    if (m0 | m1 | m2 | m3) {
        v = *(const float4*)(collab + idx);
        if (!m0) v.x = 0.f;
        if (!m1) v.y = 0.f;
        if (!m2) v.z = 0.f;
        if (!m3) v.w = 0.f;
    }
    *(float4*)(out + idx) = v;
}

extern "C" void kernel_launch(void* const* d_in, const int* in_sizes, int n_in,
                              void* d_out, int out_size) {
    const float* collab = (const float*)d_in[0];
    const float* util   = (const float*)d_in[1];
    const void*  budget = d_in[2];
    float* out     = (float*)d_out;
    float* out_sel = out + (size_t)NP * NCH;   // f_trans first, sel second

    kArgmax<<<NP/256, 256>>>(util);

    void *p_in, *p_out, *p_tmp;
    cudaGetSymbolAddress(&p_in,  g_keys_in);
    cudaGetSymbolAddress(&p_out, g_keys_out);
    cudaGetSymbolAddress(&p_tmp, g_temp);
    size_t tb = 0;
    cub::DeviceRadixSort::SortKeys(nullptr, tb,
        (const unsigned long long*)p_in, (unsigned long long*)p_out, NP, 0, 51);
    if (tb > sizeof(g_temp)) tb = sizeof(g_temp);  // (query ~MBs; buffer is 64MB)
    cub::DeviceRadixSort::SortKeys(p_tmp, tb,
        (const unsigned long long*)p_in, (unsigned long long*)p_out, NP, 0, 51);

    kScan1<<<NBLK, 256>>>();
    kScan2<<<1, NBLK>>>();
    kScan3<<<NBLK, 256>>>(budget, out_sel);
    kFixup<<<NB, 32>>>(budget, out_sel);

    kMaskedCopy<<<(NP/4)*NCH/256, 256>>>(collab, out);
}

// round 3
// speedup vs baseline: 1.8424x; 1.8424x over previous
#include <cuda_runtime.h>
#include <cstdint>

#define NB    5
#define HWPX  65536
#define NP    (NB*HWPX)
#define NCH   256
#define NBUCK 65536
#define NTILE 64            // 64 tiles of 1024 buckets per batch
#define WCAP  4096

// ---- static device scratch (allocation-free) ----
__device__ unsigned int       g_dsc[NP];           // descending-order key of best utility
__device__ unsigned char      g_g8[NP];            // argmax group 0/1/2
__device__ signed char        g_selmap[NP];        // accepted group or -1
__device__ unsigned long long g_hist[NB*NBUCK];    // packed: cost | c1<<20 | c2<<40
__device__ unsigned long long g_tile[NB*NTILE];
__device__ unsigned long long g_window[NB*WCAP];
__device__ int                g_wcount[NB];
__device__ int                g_b0[NB], g_b1[NB];
__device__ float              g_Sbefore[NB];

__device__ __forceinline__ float load_budget(const void* ptr) {
    int iv = *(const int*)ptr;                       // int32 or float32 scalar
    if (iv > 0 && iv < 100000000) return (float)iv;
    return __int_as_float(iv);
}
__device__ __forceinline__ int cost_of(int g) { return (g == 0) ? 4 : (g == 1) ? 2 : 1; }

// ---- per-pixel argmax + packed histogram ----
__global__ void kArgmax(const float* __restrict__ util) {
    int p = blockIdx.x * blockDim.x + threadIdx.x;
    float u0 = util[3*p], u1 = util[3*p+1], u2 = util[3*p+2];
    int g = 0; float bu = u0;
    if (u1 > bu) { bu = u1; g = 1; }   // strict >: first max wins (jnp.argmax)
    if (u2 > bu) { bu = u2; g = 2; }
    bool valid = bu > 0.0f;
    unsigned int x = __float_as_uint(bu);
    unsigned int dsc = ~((x & 0x80000000u) ? ~x : (x | 0x80000000u)); // descending map
    if (!valid) dsc = 0xFFFFFFFFu;
    g_dsc[p] = dsc; g_g8[p] = (unsigned char)g;
    if (valid) {
        unsigned long long inc = (unsigned long long)cost_of(g)
            | ((unsigned long long)(g == 1) << 20)
            | ((unsigned long long)(g == 2) << 40);
        atomicAdd(&g_hist[(p >> 16) * NBUCK + (dsc >> 16)], inc);
    }
}

// ---- per-tile (1024 buckets) packed sums ----
__global__ void kTileSum() {
    __shared__ unsigned long long sh[256];
    int t = threadIdx.x;
    const unsigned long long* src = g_hist + (size_t)blockIdx.x * 1024;
    sh[t] = src[t] + src[t+256] + src[t+512] + src[t+768];
    __syncthreads();
    for (int off = 128; off > 0; off >>= 1) {
        if (t < off) sh[t] += sh[t + off];
        __syncthreads();
    }
    if (t == 0) g_tile[blockIdx.x] = sh[0];
}

// ---- one block (1024 thr) per batch: find crossing bucket b0 + window end b1 ----
__global__ void kFindWindow(const void* __restrict__ budget_p) {
    __shared__ unsigned s_tile[NTILE];
    __shared__ unsigned s_wsum[32];
    __shared__ int s_ctile, s_b0;
    __shared__ unsigned s_cumbase, s_Sb;

    int b = blockIdx.x, t = threadIdx.x;
    int wid = t >> 5, lane = t & 31;
    float budget = load_budget(budget_p) / (float)NB;
    const unsigned long long* hist = g_hist + (size_t)b * NBUCK;

    if (t < NTILE) s_tile[t] = (unsigned)(g_tile[b*NTILE + t] & 0xFFFFFu);
    if (t == 0) { s_ctile = -1; s_cumbase = 0; s_b0 = NBUCK; s_Sb = 0; }
    __syncthreads();

    if (t == 0) {   // tile-level crossing (64 values in smem)
        unsigned cum = 0;
        for (int q = 0; q < NTILE; q++) {
            unsigned c = s_tile[q];
            if ((float)(cum + c) > budget) { s_ctile = q; s_cumbase = cum; break; }
            cum += c;
        }
    }
    __syncthreads();
    int ctile = s_ctile;

    if (ctile >= 0) {   // in-tile block scan over 1024 buckets (uniform branch)
        unsigned c = (unsigned)(hist[ctile*1024 + t] & 0xFFFFFu);
        unsigned inc = c;
        #pragma unroll
        for (int off = 1; off < 32; off <<= 1) {
            unsigned v = __shfl_up_sync(0xffffffffu, inc, off);
            if (lane >= off) inc += v;
        }
        if (lane == 31) s_wsum[wid] = inc;
        __syncthreads();
        if (wid == 0) {
            unsigned w = s_wsum[lane];
            #pragma unroll
            for (int off = 1; off < 32; off <<= 1) {
                unsigned v = __shfl_up_sync(0xffffffffu, w, off);
                if (lane >= off) w += v;
            }
            s_wsum[lane] = w;   // inclusive warp sums
        }
        __syncthreads();
        unsigned woff = (wid > 0) ? s_wsum[wid-1] : 0u;
        unsigned inclT = s_cumbase + woff + inc;
        unsigned excl  = inclT - c;
        if ((float)inclT > budget && (float)excl <= budget) {   // unique first crossing
            s_b0 = ctile*1024 + t;
            s_Sb = excl;
        }
        __syncthreads();
    }

    int b0 = s_b0;
    if (t < 32 && b0 < NBUCK) {
        // extend window bucket-by-bucket until >=8 cost-1 items beyond b0
        int c2cum = 0, pos = b0 + 1, b1 = 32767; bool done = false;
        while (!done && pos < 32768) {
            int idx = pos + lane;
            unsigned long long h = (idx < 32768) ? hist[idx] : 0ull;
            int k = (int)((h >> 40) & 0xFFFFFull);
            int inck = k;
            #pragma unroll
            for (int off = 1; off < 32; off <<= 1) {
                int v = __shfl_up_sync(0xffffffffu, inck, off);
                if (lane >= off) inck += v;
            }
            int tot = __shfl_sync(0xffffffffu, inck, 31);
            unsigned m = __ballot_sync(0xffffffffu, c2cum + inck >= 8);
            if (m) { b1 = min(pos + (__ffs(m) - 1), 32767); done = true; }
            else   { c2cum += tot; pos += 32; }
        }
        if (lane == 0) g_b1[b] = b1;
    }
    if (t == 0) {
        g_b0[b] = b0;
        g_Sbefore[b] = (float)s_Sb;
        if (b0 == NBUCK) g_b1[b] = -1;   // no crossing: accept all valid
    }
}

// ---- phase-1 decisions + gather window items ----
__global__ void kGather(float* __restrict__ out_sel) {
    int p = blockIdx.x * blockDim.x + threadIdx.x;
    unsigned int dsc = g_dsc[p];
    int g = (int)g_g8[p];
    int b = p >> 16;
    bool valid = dsc < 0x80000000u;
    int bucket = (int)(dsc >> 16);
    int b0 = g_b0[b], b1 = g_b1[b];
    bool acc = valid && bucket < b0;
    g_selmap[p] = acc ? (signed char)g : (signed char)-1;
    out_sel[p]  = acc ? (float)g : -1.0f;
    if (valid && bucket >= b0 && bucket <= b1) {
        int i = atomicAdd(&g_wcount[b], 1);
        if (i < WCAP)
            g_window[b*WCAP + i] = ((unsigned long long)dsc << 24)
                | ((unsigned long long)(p & 0xFFFF) << 8) | (unsigned long long)g;
    }
}

// ---- exact ranking sort + sequential greedy replay over the window ----
__global__ void kWindow(const void* __restrict__ budget_p, float* __restrict__ out_sel) {
    __shared__ unsigned long long sk[WCAP];
    int b = blockIdx.x, t = threadIdx.x;
    int n = min(g_wcount[b], WCAP);
    for (int i = t; i < n; i += 512) sk[i] = g_window[b*WCAP + i];
    __syncthreads();
    unsigned long long myk[8]; int myr[8]; int cnt = 0;
    for (int i = t; i < n; i += 512) {
        unsigned long long k = sk[i];
        int r = 0;
        for (int j = 0; j < n; j++) r += (sk[j] < k);   // keys unique -> permutation
        myk[cnt] = k; myr[cnt] = r; cnt++;
    }
    __syncthreads();
    for (int q = 0; q < cnt; q++) sk[myr[q]] = myk[q];
    __syncthreads();
    if (t == 0) {
        float budget = load_budget(budget_p) / (float)NB;
        float usage  = g_Sbefore[b];
        for (int i = 0; i < n; i++) {
            if (usage + 1.0f > budget) break;          // nothing else can fit
            unsigned long long k = sk[i];
            int g   = (int)(k & 0xFFu);
            int pix = (int)((k >> 8) & 0xFFFFu);
            float c = (float)cost_of(g);
            if (usage + c <= budget) {
                usage += c;
                int p = b * HWPX + pix;
                g_selmap[p] = (signed char)g;
                out_sel[p]  = (float)g;
            }
        }
    }
}

// ---- big HBM-bound masked channel copy ----
__global__ void kMaskedCopy(const float* __restrict__ collab, float* __restrict__ out) {
    int tid = blockIdx.x * blockDim.x + threadIdx.x;
    int row = tid >> 14;               // b*256 + c
    int o   = (tid & 16383) << 2;      // hw offset, multiple of 4
    int c   = row & 255;
    int b   = row >> 8;
    int grp = (c < 64) ? 0 : (c < 192) ? 1 : 2;
    char4 s4 = *(const char4*)(g_selmap + b * HWPX + o);
    bool m0 = (s4.x == grp), m1 = (s4.y == grp), m2 = (s4.z == grp), m3 = (s4.w == grp);
    float4 v = make_float4(0.f, 0.f, 0.f, 0.f);
    size_t idx = ((size_t)row << 16) + (size_t)o;
    if (m0 | m1 | m2 | m3) {
        v = *(const float4*)(collab + idx);
        if (!m0) v.x = 0.f;
        if (!m1) v.y = 0.f;
        if (!m2) v.z = 0.f;
        if (!m3) v.w = 0.f;
    }
    *(float4*)(out + idx) = v;
}

extern "C" void kernel_launch(void* const* d_in, const int* in_sizes, int n_in,
                              void* d_out, int out_size) {
    const float* collab = (const float*)d_in[0];
    const float* util   = (const float*)d_in[1];
    const void*  budget = d_in[2];
    float* out     = (float*)d_out;
    float* out_sel = out + (size_t)NP * NCH;

    void *p_hist, *p_wc;
    cudaGetSymbolAddress(&p_hist, g_hist);
    cudaGetSymbolAddress(&p_wc,   g_wcount);
    cudaMemsetAsync(p_hist, 0, sizeof(unsigned long long) * NB * NBUCK);
    cudaMemsetAsync(p_wc,   0, sizeof(int) * NB);

    kArgmax<<<NP/256, 256>>>(util);
    kTileSum<<<NB*NTILE, 256>>>();
    kFindWindow<<<NB, 1024>>>(budget);
    kGather<<<NP/256, 256>>>(out_sel);
    kWindow<<<NB, 512>>>(budget, out_sel);
    kMaskedCopy<<<(NP/4)*NCH/256, 256>>>(collab, out);
}